// round 6
// baseline (speedup 1.0000x reference)
#include <cuda_runtime.h>
#include <cuda_bf16.h>
#include <cstdint>

#define HF 128
#define WF 192
#define NA 9
#define HW (HF*WF)               // 24576
#define NTOT (HW*NA)             // 221184
#define TOPN 6000
#define POSTN 300
#define NB 94                    // ceil(6000/64)
#define TILE_WORDS (64*NB)       // 6016
#define CAND_MAX 16384
#define CTH 512                  // collect threads

__constant__ float c_anchors[NA][4] = {
    {-84.f,  -40.f,  99.f,  55.f},
    {-176.f, -88.f,  191.f, 103.f},
    {-360.f, -184.f, 375.f, 199.f},
    {-56.f,  -56.f,  71.f,  71.f},
    {-120.f, -120.f, 135.f, 135.f},
    {-248.f, -248.f, 263.f, 263.f},
    {-36.f,  -80.f,  51.f,  95.f},
    {-80.f,  -168.f, 95.f,  183.f},
    {-168.f, -344.f, 183.f, 359.f}
};

// single zeroed region (one memset node)
struct ZeroBlock {
    unsigned int hist[65536];
    unsigned long long sup[NB];
};
__device__ __align__(16) ZeroBlock g_z;

__device__ unsigned long long g_keys[NTOT];
__device__ __align__(16) unsigned int g_sfx[65536];  // sfx[b] = #keys in buckets > b
__device__ unsigned int g_thresh;
__device__ unsigned int g_cand_count;
__device__ __align__(16) unsigned long long g_cand[CAND_MAX];
__device__ float4 g_top_boxes[TOPN];
__device__ unsigned long long g_mask[6016 * NB];

__device__ __forceinline__ void cp_async8(void* smem_dst, const void* gmem_src) {
    unsigned int d = (unsigned int)__cvta_generic_to_shared(smem_dst);
    asm volatile("cp.async.ca.shared.global [%0], [%1], 8;" :: "r"(d), "l"(gmem_src) : "memory");
}
__device__ __forceinline__ void cp_async_commit() {
    asm volatile("cp.async.commit_group;" ::: "memory");
}
__device__ __forceinline__ void cp_async_wait0() {
    asm volatile("cp.async.wait_group 0;" ::: "memory");
}

// shared decode (used by K1 for validity/score and by ranksc for the box)
__device__ __forceinline__ float4 decode_box(int a, int k,
                                             const float* __restrict__ deltas,
                                             float im0, float im1, float im2,
                                             bool* valid) {
    int xs = k >> 7;          // meshgrid 'ij' quirk: shift row k -> (x=k/128, y=k%128)
    int ys = k & 127;
    float dx = deltas[(4*a + 0) * HW + k];
    float dy = deltas[(4*a + 1) * HW + k];
    float dw = deltas[(4*a + 2) * HW + k];
    float dh = deltas[(4*a + 3) * HW + k];

    float sx = 16.f * (float)xs;
    float sy = 16.f * (float)ys;
    float ax1 = c_anchors[a][0] + sx;
    float ay1 = c_anchors[a][1] + sy;
    float ax2 = c_anchors[a][2] + sx;
    float ay2 = c_anchors[a][3] + sy;

    float w = ax2 - ax1 + 1.f;
    float h = ay2 - ay1 + 1.f;
    float cx = ax1 + 0.5f * w;
    float cy = ay1 + 0.5f * h;

    float pcx = dx * w + cx;
    float pcy = dy * h + cy;
    float pw = expf(dw) * w;
    float ph = expf(dh) * h;

    float x1 = pcx - 0.5f * pw;
    float y1 = pcy - 0.5f * ph;
    float x2 = pcx + 0.5f * pw;
    float y2 = pcy + 0.5f * ph;

    x1 = fminf(fmaxf(x1, 0.f), im1 - 1.f);
    x2 = fminf(fmaxf(x2, 0.f), im1 - 1.f);
    y1 = fminf(fmaxf(y1, 0.f), im0 - 1.f);
    y2 = fminf(fmaxf(y2, 0.f), im0 - 1.f);

    float ms = 16.f * im2;
    *valid = (x2 - x1 + 1.f >= ms) && (y2 - y1 + 1.f >= ms);
    return make_float4(x1, y1, x2, y2);
}

// ---------------- K1: keys + histogram only ----------------
__global__ void k_score_box(const float* __restrict__ scores,
                            const float* __restrict__ deltas,
                            const float* __restrict__ im_info) {
    int t = blockIdx.x * blockDim.x + threadIdx.x;
    if (t >= NTOT) return;
    int a = t / HW;
    int k = t - a * HW;
    int i_ref = k * NA + a;   // reference flatten order (tiebreak)

    float sc = scores[(NA + a) * HW + k];
    float im0 = im_info[0], im1 = im_info[1], im2 = im_info[2];
    bool valid;
    (void)decode_box(a, k, deltas, im0, im1, im2, &valid);

    unsigned int srt;
    if (valid) {
        unsigned int b = __float_as_uint(sc);
        srt = (b & 0x80000000u) ? ~b : (b | 0x80000000u);
    } else {
        srt = 0x007FFFFFu;   // flip(-inf)
    }
    unsigned long long key =
        ((unsigned long long)srt << 32) | (0xFFFFFFFFu - (unsigned int)i_ref);
    g_keys[t] = key;
    atomicAdd(&g_z.hist[srt >> 16], 1u);
}

// ---------------- K2: suffix table + threshold + candidate count ----------------
__global__ void k_thresh() {
    __shared__ unsigned int s[256];
    __shared__ unsigned int S2[256];
    __shared__ int gsel;
    __shared__ unsigned int above_s;
    int t = threadIdx.x;
    unsigned int sum = 0;
    const uint4* h4 = (const uint4*)g_z.hist;
#pragma unroll 8
    for (int b = 0; b < 64; b++) {
        uint4 v = h4[t * 64 + b];
        sum += v.x + v.y + v.z + v.w;
    }
    s[t] = sum;
    __syncthreads();
    for (int off = 1; off < 256; off <<= 1) {
        unsigned int v = (t + off < 256) ? s[t + off] : 0u;
        __syncthreads();
        s[t] += v;
        __syncthreads();
    }
    S2[t] = s[t];              // group suffix sums (keys in groups >= t)
    __syncthreads();

    // full per-bucket suffix table, vectorized
    {
        unsigned int run = (t == 255) ? 0u : S2[t + 1];
        uint4* s4 = (uint4*)g_sfx;
#pragma unroll 4
        for (int q = 63; q >= 0; q--) {
            int idx4 = t * 64 + q;
            uint4 h = h4[idx4];
            uint4 o;
            o.w = run; run += h.w;
            o.z = run; run += h.z;
            o.y = run; run += h.y;
            o.x = run; run += h.x;
            s4[idx4] = o;
        }
    }

    unsigned int nxt = (t == 255) ? 0u : S2[t + 1];
    if (S2[t] >= TOPN && nxt < TOPN) { gsel = t; above_s = nxt; }
    __syncthreads();
    int g = gsel;
    unsigned int above = above_s;
    unsigned int fv = g_z.hist[g * 256 + t];
    __syncthreads();
    s[t] = fv;
    __syncthreads();
    for (int off = 1; off < 256; off <<= 1) {
        unsigned int v = (t + off < 256) ? s[t + off] : 0u;
        __syncthreads();
        s[t] += v;
        __syncthreads();
    }
    unsigned int nxt2 = (t == 255) ? 0u : s[t + 1];
    if (above + s[t] >= TOPN && above + nxt2 < TOPN) {
        g_thresh = (unsigned int)(g * 256 + t);
        g_cand_count = above + s[t];
    }
}

// ---------------- K3: compact candidates into bucket-ordered slots ----------------
__global__ void k_compact() {
    int i = blockIdx.x * blockDim.x + threadIdx.x;
    if (i >= NTOT) return;
    unsigned long long key = g_keys[i];
    unsigned int b = (unsigned int)(key >> 48);
    if (b >= g_thresh) {
        unsigned int end = (b > 0) ? g_sfx[b - 1] : (unsigned int)NTOT; // block end
        unsigned int old = atomicSub(&g_z.hist[b], 1u);                  // counts down
        unsigned int slot = end - old;                                   // bucket base .. end-1
        if (slot < CAND_MAX) g_cand[slot] = key;
    }
}

// ---------------- K4: in-bucket exact rank + decode + scatter ----------------
__global__ void k_ranksc(const float* __restrict__ deltas,
                         const float* __restrict__ im_info) {
    unsigned int C = g_cand_count;
    if (C > CAND_MAX) C = CAND_MAX;
    int i = blockIdx.x * blockDim.x + threadIdx.x;
    if (i >= (int)C) return;
    unsigned long long mykey = g_cand[i];
    unsigned int b = (unsigned int)(mykey >> 48);
    unsigned int base = g_sfx[b];
    unsigned int end = (b > 0) ? g_sfx[b - 1] : C;
    if (end > C) end = C;
    unsigned int rank = base;
    for (unsigned int j = base; j < end; j++)
        rank += (g_cand[j] > mykey) ? 1u : 0u;
    if (rank < TOPN) {
        unsigned int idx = 0xFFFFFFFFu - (unsigned int)(mykey & 0xFFFFFFFFull);
        int a = idx % NA;
        int k = idx / NA;
        float im0 = im_info[0], im1 = im_info[1], im2 = im_info[2];
        bool valid;
        float4 box = decode_box(a, k, deltas, im0, im1, im2, &valid);
        g_top_boxes[rank] = box;
        bool vkey = ((unsigned int)(mykey >> 32)) > 0x007FFFFFu;
        if (!vkey) atomicOr(&g_z.sup[rank >> 6], 1ull << (rank & 63));
    }
}

// ---------------- K5: NMS suppression bitmask (upper triangle only) ----------------
__global__ void k_mask() {
    int bi = blockIdx.y, bj = blockIdx.x;
    if (bj < bi) return;
    int t = threadIdx.x;
    int i = bi * 64 + t;
    __shared__ float4 bb[64];
    __shared__ float ar[64];
    int jg0 = bj * 64 + t;
    if (jg0 < TOPN) {
        float4 b = g_top_boxes[jg0];
        bb[t] = b;
        ar[t] = (b.z - b.x) * (b.w - b.y);
    } else {
        bb[t] = make_float4(0.f, 0.f, 0.f, 0.f);
        ar[t] = 0.f;
    }
    __syncthreads();
    if (i >= TOPN) return;
    float4 bi_box = g_top_boxes[i];
    float area_i = (bi_box.z - bi_box.x) * (bi_box.w - bi_box.y);
    unsigned long long m = 0ull;
#pragma unroll 4
    for (int jj = 0; jj < 64; jj++) {
        int jg = bj * 64 + jj;
        float4 bj_box = bb[jj];
        float ix1 = fmaxf(bi_box.x, bj_box.x);
        float iy1 = fmaxf(bi_box.y, bj_box.y);
        float ix2 = fminf(bi_box.z, bj_box.z);
        float iy2 = fminf(bi_box.w, bj_box.w);
        float inter = fmaxf(ix2 - ix1, 0.f) * fmaxf(iy2 - iy1, 0.f);
        float denom = fmaxf(area_i + ar[jj] - inter, 1e-9f);
        float iou = inter / denom;
        if (iou > 0.7f && jg > i && jg < TOPN) m |= (1ull << jj);
    }
    g_mask[(size_t)i * NB + bj] = m;
}

// ---------------- K6: greedy collect, deferred-OR, cp.async double buffer ----
// Control flow uniform across block (branch data identical per thread).
__global__ void __launch_bounds__(CTH) k_collect(float* __restrict__ out) {
    __shared__ unsigned long long remv[NB];
    __shared__ int klist[POSTN];
    extern __shared__ unsigned long long tiles[];  // 2 * TILE_WORDS
    int tid = threadIdx.x;

    // zero output (d_out is poisoned)
    for (int t = tid; t < POSTN * 5; t += CTH) out[t] = 0.f;

    for (int t = tid; t < NB; t += CTH) {
        unsigned long long m = g_z.sup[t];
        if (t == NB - 1) m |= 0xFFFF000000000000ull;   // bits 48..63 (>= 6000)
        remv[t] = m;
    }

    // prefetch tile 0
    {
        int wcnt = NB;
        for (int t = tid; t < 64 * wcnt; t += CTH) {
            int r = t / wcnt, w = t - r * wcnt;
            cp_async8(&tiles[t], &g_mask[(size_t)r * NB + w]);
        }
        cp_async_commit();
    }
    cp_async_wait0();
    __syncthreads();

    int kept = 0;
    for (int ib = 0; ib < NB; ib++) {
        unsigned long long* tile = tiles + (size_t)(ib & 1) * TILE_WORDS;
        // issue prefetch of next tile into the other buffer
        if (ib + 1 < NB) {
            int nb2 = ib + 1;
            int wcnt2 = NB - nb2;
            int rows2 = TOPN - nb2 * 64; if (rows2 > 64) rows2 = 64;
            unsigned long long* dst = tiles + (size_t)(nb2 & 1) * TILE_WORDS;
            for (int t = tid; t < rows2 * wcnt2; t += CTH) {
                int r = t / wcnt2, w = t - r * wcnt2;
                cp_async8(&dst[t], &g_mask[(size_t)(nb2 * 64 + r) * NB + nb2 + w]);
            }
        }
        cp_async_commit();

        int wcnt = NB - ib;
        unsigned long long rcur = remv[ib];
        unsigned long long acc = 0ull;
        int w = tid;                       // this thread owns word ib+w (w<wcnt)
        while (true) {
            unsigned long long avail = ~rcur;
            if (avail == 0ull) break;
            int bit = __ffsll((long long)avail) - 1;
            if (tid == 0) klist[kept] = ib * 64 + bit;
            kept++;
            rcur |= tile[bit * wcnt] | (1ull << bit);      // self word + mark done
            if (w > 0 && w < wcnt) acc |= tile[bit * wcnt + w];
            if (kept >= POSTN) break;
        }
        if (w > 0 && w < wcnt) remv[ib + w] |= acc;
        if (kept >= POSTN) break;
        cp_async_wait0();
        __syncthreads();
    }

    cp_async_wait0();
    __syncthreads();
    if (tid < kept) {
        int idx = klist[tid];
        float4 b = g_top_boxes[idx];
        float* row = out + tid * 5;
        row[0] = 0.f; row[1] = b.x; row[2] = b.y; row[3] = b.z; row[4] = b.w;
    }
}

extern "C" void kernel_launch(void* const* d_in, const int* in_sizes, int n_in,
                              void* d_out, int out_size) {
    const float* scores  = (const float*)d_in[0];
    const float* deltas  = (const float*)d_in[1];
    const float* im_info = (const float*)d_in[2];
    float* out = (float*)d_out;

    void* p;
    cudaGetSymbolAddress(&p, g_z);
    cudaMemsetAsync(p, 0, sizeof(ZeroBlock));

    k_score_box<<<(NTOT + 255) / 256, 256>>>(scores, deltas, im_info);
    k_thresh<<<1, 256>>>();
    k_compact<<<(NTOT + 255) / 256, 256>>>();
    k_ranksc<<<CAND_MAX / 256, 256>>>(deltas, im_info);

    dim3 gm(NB, NB);
    k_mask<<<gm, 64>>>();

    size_t csh = (size_t)2 * TILE_WORDS * sizeof(unsigned long long);
    cudaFuncSetAttribute(k_collect, cudaFuncAttributeMaxDynamicSharedMemorySize, (int)csh);
    k_collect<<<1, CTH, csh>>>(out);
}